// round 16
// baseline (speedup 1.0000x reference)
#include <cuda_runtime.h>
#include <cuda_fp16.h>
#include <cstdint>
#include <cstddef>

// ---------------------------------------------------------------------------
// MultiHeadAttention: B=4, S=2048, D=256, H=8, HD=2048
// R16 = R15 (all GEMMs fp16 m16n8k16 + ldmatrix, fp32 accum) with ONE change:
// software-pipelined fragments. Each warp double-buffers its A/B ldmatrix
// fragments and prefetches step ks+1 while issuing MMAs for ks, overlapping
// the LDS crossbar with the tensor pipe (ncu showed them co-binding ~50%
// each, serialized). Register cost +32 -> __launch_bounds__(128, 2).
//   0. merged fp32->fp16 RNE conversion of inputs + weights
//   1. merged Q/K/V projections NT [8192,2048,256] + bias -> half
//   2. V transpose per head (raw-reshape slice) -> VT[32][256][2048]
//   3. E = exp(Q_h K_h^T /16): NT, half E + fp32 l partials
//   4. O = (E VT^T)/l: NT [2048,256,2048], ldb=2048 -> half o (transposed)
//   5. y = o @ Wo^T + bo: NT [8192,256,2048] -> fp32 out
// ---------------------------------------------------------------------------

static const int B_ = 4, S_ = 2048, D_ = 256, H_ = 8, HD_ = 2048;

__device__ __half g_q[(size_t)4 * 2048 * 2048];    //  32 MB proj Q
__device__ __half g_k[(size_t)4 * 2048 * 2048];    //  32 MB proj K
__device__ __half g_v[(size_t)4 * 2048 * 2048];    //  32 MB proj V
__device__ __half g_vt[(size_t)32 * 256 * 2048];   //  32 MB V^T per head
__device__ __half g_e[(size_t)32 * 2048 * 2048];   // 256 MB exp(scores)
__device__ __half g_o[(size_t)4 * 2048 * 2048];    //  32 MB attn out (transposed)
__device__ float  g_l[(size_t)32 * 2048 * 16];     //   4 MB row-sum partials
__device__ __half g_rq[2097152], g_rk[2097152], g_rv[2097152];
__device__ __half g_wq[524288], g_wk[524288], g_wv[524288], g_wo[524288];

__device__ __forceinline__ void cp_async16(uint32_t saddr, const void* g) {
    asm volatile("cp.async.cg.shared.global [%0], [%1], 16;" :: "r"(saddr), "l"(g));
}
#define CP_COMMIT() asm volatile("cp.async.commit_group;" ::: "memory")
#define CP_WAIT0()  asm volatile("cp.async.wait_group 0;" ::: "memory")
#define CP_WAIT1()  asm volatile("cp.async.wait_group 1;" ::: "memory")

__device__ __forceinline__ uint32_t smem_u32(const void* p) {
    uint32_t a;
    asm("{ .reg .u64 t; cvta.to.shared.u64 t, %1; cvt.u32.u64 %0, t; }"
        : "=r"(a) : "l"(p));
    return a;
}
__device__ __forceinline__ void mma_f16(float c[4],
    uint32_t a0, uint32_t a1, uint32_t a2, uint32_t a3,
    uint32_t b0, uint32_t b1)
{
    asm volatile(
        "mma.sync.aligned.m16n8k16.row.col.f32.f16.f16.f32 "
        "{%0,%1,%2,%3}, {%4,%5,%6,%7}, {%8,%9}, {%0,%1,%2,%3};\n"
        : "+f"(c[0]), "+f"(c[1]), "+f"(c[2]), "+f"(c[3])
        : "r"(a0), "r"(a1), "r"(a2), "r"(a3), "r"(b0), "r"(b1));
}
__device__ __forceinline__ void ldsm_x4(uint32_t& r0, uint32_t& r1,
                                        uint32_t& r2, uint32_t& r3, uint32_t a)
{
    asm volatile("ldmatrix.sync.aligned.m8n8.x4.shared.b16 {%0,%1,%2,%3}, [%4];"
                 : "=r"(r0), "=r"(r1), "=r"(r2), "=r"(r3) : "r"(a));
}

// ---------------------------------------------------------------------------
// Merged fp32 -> fp16 (RNE): 3 inputs (2M floats) + 4 weights (512K)
// ---------------------------------------------------------------------------
__global__ void __launch_bounds__(256) round_all(
    const float* __restrict__ q, const float* __restrict__ k,
    const float* __restrict__ v,
    const float* __restrict__ wq, const float* __restrict__ wk,
    const float* __restrict__ wv, const float* __restrict__ wo,
    __half* __restrict__ rq, __half* __restrict__ rk, __half* __restrict__ rv,
    __half* __restrict__ owq, __half* __restrict__ owk,
    __half* __restrict__ owv, __half* __restrict__ owo)
{
    int i = blockIdx.x * 256 + threadIdx.x;
    const float* src; __half* dst; int off;
    if (i < 1572864) {
        int s = i / 524288; off = i - s * 524288;
        src = s == 0 ? q : s == 1 ? k : v;
        dst = s == 0 ? rq : s == 1 ? rk : rv;
    } else {
        int j = i - 1572864;
        int s = j / 131072; off = j - s * 131072;
        src = s == 0 ? wq : s == 1 ? wk : s == 2 ? wv : wo;
        dst = s == 0 ? owq : s == 1 ? owk : s == 2 ? owv : owo;
    }
    float4 x = ((const float4*)src)[off];
    ((__half2*)dst)[2 * off]     = __floats2half2_rn(x.x, x.y);
    ((__half2*)dst)[2 * off + 1] = __floats2half2_rn(x.z, x.w);
}

// ---------------------------------------------------------------------------
// V transpose per head (RAW-RESHAPE slice):
//   V_h[s][d] = v[z*524288 + s*256 + d]   (z = b*8 + h)
//   vt[z][d][s] = V_h[s][d]
// ---------------------------------------------------------------------------
__global__ void __launch_bounds__(256) transpose_v(
    const __half* __restrict__ v, __half* __restrict__ vt)
{
    __shared__ __half t[32][34];
    const int z = blockIdx.z;
    const int s0 = blockIdx.x * 32, d0 = blockIdx.y * 32;
    const int tx = threadIdx.x, ty = threadIdx.y;

    const __half* src = v + (size_t)z * 524288 + (size_t)s0 * 256 + d0;
#pragma unroll
    for (int i = ty; i < 32; i += 8)
        t[i][tx] = src[(size_t)i * 256 + tx];
    __syncthreads();
    __half* dst = vt + (size_t)z * 524288 + (size_t)d0 * 2048 + s0;
#pragma unroll
    for (int i = ty; i < 32; i += 8)
        dst[(size_t)i * 2048 + tx] = t[tx][i];
}

// ---------------------------------------------------------------------------
// fp16 NT GEMM body: C[128y,128x] = A[M,K] @ B[N,K]^T
// A,B half K-contig; BK=64 halfs staged [128 rows][144 B]; fragments via
// ldmatrix.x4, DOUBLE-BUFFERED in registers with ks+1 prefetch (R16).
// EPI 0: +bias -> half | 1: exp(acc/16) -> half E + fp32 l partials
// EPI 2: scale 1/l -> half | 3: +bias -> float
// ---------------------------------------------------------------------------
#define OP_BYTES    18432
#define STAGE_BYTES (2 * OP_BYTES)
#define RED_OFF     (2 * STAGE_BYTES / 4)          // float index
#define GEMM_SMEM   (2 * STAGE_BYTES + 1024)       // 74752 B

template<int EPI>
__device__ __forceinline__ void gemm_body(
    const __half* __restrict__ A, const __half* __restrict__ B,
    const float* __restrict__ bias, void* __restrict__ Cv,
    float* __restrict__ lbase,
    int K, int lda, int ldb, int ldc, int lx)
{
    extern __shared__ __align__(16) float smem[];
    const uint32_t sbase = smem_u32(smem);
    const int tid  = threadIdx.x;
    const int lane = tid & 31;
    const int warp = tid >> 5;
    const int g = lane >> 2;
    const int t = lane & 3;
    const int wm0 = (warp >> 1) * 64;
    const int wn0 = (warp & 1) * 64;

    const int row0 = blockIdx.y * 128;
    const int col0 = blockIdx.x * 128;
    A += (size_t)row0 * lda;
    B += (size_t)col0 * ldb;
    const int nch = K >> 6;

    if (EPI == 2) {             // prologue: 1/l per row
        if (tid < 128) {
            const float* lp = lbase + (size_t)(row0 + tid) * 16;
            float4 a4 = *(const float4*)(lp);
            float4 b4 = *(const float4*)(lp + 4);
            float4 c4 = *(const float4*)(lp + 8);
            float4 d4 = *(const float4*)(lp + 12);
            float s = (a4.x + a4.y + a4.z + a4.w) + (b4.x + b4.y + b4.z + b4.w)
                    + (c4.x + c4.y + c4.z + c4.w) + (d4.x + d4.y + d4.z + d4.w);
            smem[RED_OFF + tid] = 1.0f / s;
        }
    }

    const int ar = tid >> 3, ac = tid & 7;

    auto stage = [&](int chunk) {
        const uint32_t abuf = sbase + (chunk & 1) * STAGE_BYTES;
        const uint32_t bbuf = abuf + OP_BYTES;
        const __half* Ak = A + chunk * 64;
        const __half* Bk = B + chunk * 64;
#pragma unroll
        for (int i = 0; i < 8; i++) {
            int r = ar + i * 16;
            cp_async16(abuf + r * 144 + ac * 16, Ak + (size_t)r * lda + ac * 8);
            cp_async16(bbuf + r * 144 + ac * 16, Bk + (size_t)r * ldb + ac * 8);
        }
        CP_COMMIT();
    };

    // ldmatrix lane->address selectors (R13-validated)
    const int a_row = ((lane >> 3) & 1) * 8 + (lane & 7);
    const int a_k   = (lane >> 4) * 8;
    const int b_n   = (lane >> 4) * 8 + (lane & 7);
    const int b_k   = ((lane >> 3) & 1) * 8;

    float acc[4][8][4];
#pragma unroll
    for (int i = 0; i < 4; i++)
#pragma unroll
        for (int j = 0; j < 8; j++)
#pragma unroll
            for (int l = 0; l < 4; l++) acc[i][j][l] = 0.0f;

    // double-buffered fragments (R16)
    uint32_t afr[2][4][4], bfr[2][8][2];

    auto load_frags = [&](int buf, uint32_t As, uint32_t Bs, int ks) {
#pragma unroll
        for (int np = 0; np < 4; np++) {
            uint32_t baddr = Bs +
                (uint32_t)((wn0 + np * 16 + b_n) * 144 + (ks + b_k) * 2);
            ldsm_x4(bfr[buf][2 * np][0], bfr[buf][2 * np][1],
                    bfr[buf][2 * np + 1][0], bfr[buf][2 * np + 1][1], baddr);
        }
#pragma unroll
        for (int mt = 0; mt < 4; mt++) {
            uint32_t aaddr = As +
                (uint32_t)((wm0 + mt * 16 + a_row) * 144 + (ks + a_k) * 2);
            ldsm_x4(afr[buf][mt][0], afr[buf][mt][1],
                    afr[buf][mt][2], afr[buf][mt][3], aaddr);
        }
    };

    stage(0);
    for (int i = 0; i < nch; i++) {
        if (i + 1 < nch) { stage(i + 1); CP_WAIT1(); }
        else             { CP_WAIT0(); }
        __syncthreads();

        const uint32_t As = sbase + (i & 1) * STAGE_BYTES;
        const uint32_t Bs = As + OP_BYTES;
        load_frags(0, As, Bs, 0);
#pragma unroll
        for (int ks16 = 0; ks16 < 4; ks16++) {
            const int cur = ks16 & 1;
            if (ks16 < 3) load_frags(cur ^ 1, As, Bs, (ks16 + 1) * 16);
#pragma unroll
            for (int mt = 0; mt < 4; mt++)
#pragma unroll
                for (int nt = 0; nt < 8; nt++)
                    mma_f16(acc[mt][nt],
                            afr[cur][mt][0], afr[cur][mt][1],
                            afr[cur][mt][2], afr[cur][mt][3],
                            bfr[cur][nt][0], bfr[cur][nt][1]);
        }
        __syncthreads();
    }

    // ------------------- epilogues -------------------
    if (EPI == 1) {
        __half* C = (__half*)Cv;
        float* rs2 = smem + RED_OFF;          // [128][2]
#pragma unroll
        for (int mt = 0; mt < 4; mt++) {
            float ra = 0.0f, rb = 0.0f;
            int rA = row0 + wm0 + mt * 16 + g;
#pragma unroll
            for (int nt = 0; nt < 8; nt++) {
                int c = col0 + wn0 + nt * 8 + 2 * t;
                float e0 = __expf(acc[mt][nt][0] * 0.0625f);
                float e1 = __expf(acc[mt][nt][1] * 0.0625f);
                float e2 = __expf(acc[mt][nt][2] * 0.0625f);
                float e3 = __expf(acc[mt][nt][3] * 0.0625f);
                ra += e0 + e1;
                rb += e2 + e3;
                *(__half2*)(C + (size_t)rA * ldc + c) = __floats2half2_rn(e0, e1);
                *(__half2*)(C + (size_t)(rA + 8) * ldc + c) = __floats2half2_rn(e2, e3);
            }
            ra += __shfl_xor_sync(0xffffffffu, ra, 1);
            ra += __shfl_xor_sync(0xffffffffu, ra, 2);
            rb += __shfl_xor_sync(0xffffffffu, rb, 1);
            rb += __shfl_xor_sync(0xffffffffu, rb, 2);
            if (t == 0) {
                rs2[(wm0 + mt * 16 + g) * 2 + (warp & 1)]     = ra;
                rs2[(wm0 + mt * 16 + g + 8) * 2 + (warp & 1)] = rb;
            }
        }
        __syncthreads();
        if (tid < 128) {
            lbase[(size_t)(row0 + tid) * 16 + lx] =
                rs2[tid * 2] + rs2[tid * 2 + 1];
        }
        return;
    }

#pragma unroll
    for (int mt = 0; mt < 4; mt++) {
        float lv0 = 1.0f, lv1 = 1.0f;
        if (EPI == 2) {
            lv0 = smem[RED_OFF + wm0 + mt * 16 + g];
            lv1 = smem[RED_OFF + wm0 + mt * 16 + g + 8];
        }
#pragma unroll
        for (int nt = 0; nt < 8; nt++) {
            int r = row0 + wm0 + mt * 16 + g;
            int c = col0 + wn0 + nt * 8 + 2 * t;
            float b0v = ((EPI == 0 || EPI == 3) && bias) ? bias[c]     : 0.0f;
            float b1v = ((EPI == 0 || EPI == 3) && bias) ? bias[c + 1] : 0.0f;
            float v0x = acc[mt][nt][0] * lv0 + b0v;
            float v0y = acc[mt][nt][1] * lv0 + b1v;
            float v1x = acc[mt][nt][2] * lv1 + b0v;
            float v1y = acc[mt][nt][3] * lv1 + b1v;
            if (EPI == 3) {
                float* C = (float*)Cv;
                *(float2*)(C + (size_t)r * ldc + c)       = make_float2(v0x, v0y);
                *(float2*)(C + (size_t)(r + 8) * ldc + c) = make_float2(v1x, v1y);
            } else {
                __half* C = (__half*)Cv;
                *(__half2*)(C + (size_t)r * ldc + c)       = __floats2half2_rn(v0x, v0y);
                *(__half2*)(C + (size_t)(r + 8) * ldc + c) = __floats2half2_rn(v1x, v1y);
            }
        }
    }
}

// ---------------------------------------------------------------------------
// wrappers (occupancy 2 -> 256-reg budget for the fragment double buffer)
// ---------------------------------------------------------------------------
template<int EPI>
__global__ void __launch_bounds__(128, 2) gemm_ws(
    const __half* __restrict__ A, const __half* __restrict__ B,
    const float* __restrict__ bias, void* __restrict__ Cv,
    float* __restrict__ lbuf,
    int K, int lda, int ldb, int ldc,
    long long sA, long long sB, int Hp, long long sC_b, long long sC_h)
{
    const int z = blockIdx.z;
    long long coff = (long long)(z / Hp) * sC_b + (long long)(z % Hp) * sC_h;
    void* C = (EPI == 3) ? (void*)((float*)Cv + coff)
                         : (void*)((__half*)Cv + coff);
    gemm_body<EPI>(A + (long long)z * sA, B + (long long)z * sB, bias, C,
                   lbuf ? lbuf + (size_t)z * 2048 * 16 : nullptr,
                   K, lda, ldb, ldc, blockIdx.x);
}

__global__ void __launch_bounds__(128, 2) gemm_qkv(
    const __half* A0, const __half* A1, const __half* A2,
    const __half* W0, const __half* W1, const __half* W2,
    const float* b0, const float* b1, const float* b2,
    __half* C0, __half* C1, __half* C2,
    int K, int lda, int ldb, int ldc)
{
    const int z = blockIdx.z;
    const __half* A = z == 0 ? A0 : z == 1 ? A1 : A2;
    const __half* W = z == 0 ? W0 : z == 1 ? W1 : W2;
    const float* bb = z == 0 ? b0 : z == 1 ? b1 : b2;
    __half* C = z == 0 ? C0 : z == 1 ? C1 : C2;
    gemm_body<0>(A, W, bb, C, nullptr, K, lda, ldb, ldc, 0);
}

// ---------------------------------------------------------------------------
extern "C" void kernel_launch(void* const* d_in, const int* in_sizes, int n_in,
                              void* d_out, int out_size)
{
    const float* query = (const float*)d_in[0];
    const float* key   = (const float*)d_in[1];
    const float* vals  = (const float*)d_in[2];
    const float* Wq    = (const float*)d_in[3];
    const float* bq    = (const float*)d_in[4];
    const float* Wk    = (const float*)d_in[5];
    const float* bk    = (const float*)d_in[6];
    const float* Wv    = (const float*)d_in[7];
    const float* bv    = (const float*)d_in[8];
    const float* Wo    = (const float*)d_in[9];
    const float* bo    = (const float*)d_in[10];
    float* out = (float*)d_out;

    __half *q, *k, *v, *vt, *e, *o, *rq, *rk, *rv, *wq, *wk, *wv, *wo;
    float* l;
    cudaGetSymbolAddress((void**)&q,  g_q);
    cudaGetSymbolAddress((void**)&k,  g_k);
    cudaGetSymbolAddress((void**)&v,  g_v);
    cudaGetSymbolAddress((void**)&vt, g_vt);
    cudaGetSymbolAddress((void**)&e,  g_e);
    cudaGetSymbolAddress((void**)&o,  g_o);
    cudaGetSymbolAddress((void**)&l,  g_l);
    cudaGetSymbolAddress((void**)&rq, g_rq);
    cudaGetSymbolAddress((void**)&rk, g_rk);
    cudaGetSymbolAddress((void**)&rv, g_rv);
    cudaGetSymbolAddress((void**)&wq, g_wq);
    cudaGetSymbolAddress((void**)&wk, g_wk);
    cudaGetSymbolAddress((void**)&wv, g_wv);
    cudaGetSymbolAddress((void**)&wo, g_wo);

    cudaFuncSetAttribute(gemm_qkv,
                         cudaFuncAttributeMaxDynamicSharedMemorySize, GEMM_SMEM);
    cudaFuncSetAttribute(gemm_ws<1>,
                         cudaFuncAttributeMaxDynamicSharedMemorySize, GEMM_SMEM);
    cudaFuncSetAttribute(gemm_ws<2>,
                         cudaFuncAttributeMaxDynamicSharedMemorySize, GEMM_SMEM);
    cudaFuncSetAttribute(gemm_ws<3>,
                         cudaFuncAttributeMaxDynamicSharedMemorySize, GEMM_SMEM);

    const int B = B_, S = S_, D = D_, HD = HD_;
    dim3 blk(128);
    size_t sm = GEMM_SMEM;

    // 0. fp32 -> fp16 (RNE)
    round_all<<<8192, 256>>>(query, key, vals, Wq, Wk, Wv, Wo,
                             rq, rk, rv, wq, wk, wv, wo);

    // 1. merged Q/K/V projections, K=256 -> half
    dim3 gp(HD / 128, (B * S) / 128, 3);
    gemm_qkv<<<gp, blk, sm>>>(rq, rk, rv, wq, wk, wv, bq, bk, bv,
                              q, k, v, D, D, D, HD);

    // 2. V transpose per head (raw-reshape slice) -> vt[z][d][s]
    transpose_v<<<dim3(S / 32, D / 32, B * H_), dim3(32, 8)>>>(v, vt);

    // 3. E = exp(Q_h K_h^T / 16) + l partials, K=256 (half E)
    dim3 gs(S / 128, S / 128, B * H_);
    gemm_ws<1><<<gs, blk, sm>>>(q, k, nullptr, e, l,
        D, D, D, S,
        (long long)S * D, (long long)S * D, 1, (long long)S * S, 0);

    // 4. O = (E VT^T) / l -> transposed layout, K=2048, ldb=2048
    dim3 gv(D / 128, S / 128, B * H_);
    gemm_ws<2><<<gv, blk, sm>>>(e, vt, nullptr, o, l,
        S, S, S, HD,
        (long long)S * S, (long long)D * S,
        H_, (long long)S * HD, (long long)D);

    // 5. y = o @ Wo^T + bo (fp32 output), K=2048
    dim3 gf(D / 128, (B * S) / 128, 1);
    gemm_ws<3><<<gf, blk, sm>>>(o, wo, bo, out, nullptr,
        HD, HD, HD, D, 0, 0, 1, 0, 0);
}

// round 17
// speedup vs baseline: 1.0266x; 1.0266x over previous
#include <cuda_runtime.h>
#include <cuda_fp16.h>
#include <cstdint>
#include <cstddef>

// ---------------------------------------------------------------------------
// MultiHeadAttention: B=4, S=2048, D=256, H=8, HD=2048
// R17 = R15 (all GEMMs fp16 m16n8k16 + ldmatrix, fp32 accum, 3 CTAs/SM)
// + split-K(4) out-projection: grid was 128 CTAs (<30% of chip); now 512
// CTAs each K=512 -> fp32 partials, then a reduce(+bias) kernel.
//   0. merged fp32->fp16 RNE conversion of inputs + weights
//   1. merged Q/K/V projections NT [8192,2048,256] + bias -> half
//   2. V transpose per head (raw-reshape slice) -> VT[32][256][2048]
//   3. E = exp(Q_h K_h^T /16): NT, half E + fp32 l partials
//   4. O = (E VT^T)/l: NT [2048,256,2048], ldb=2048 -> half o (transposed)
//   5. y partials = o @ Wo^T (split-K 4) -> fp32 [4][8192][256]
//   6. y = sum partials + bo -> fp32 out
// ---------------------------------------------------------------------------

static const int B_ = 4, S_ = 2048, D_ = 256, H_ = 8, HD_ = 2048;

__device__ __half g_q[(size_t)4 * 2048 * 2048];    //  32 MB proj Q
__device__ __half g_k[(size_t)4 * 2048 * 2048];    //  32 MB proj K
__device__ __half g_v[(size_t)4 * 2048 * 2048];    //  32 MB proj V
__device__ __half g_vt[(size_t)32 * 256 * 2048];   //  32 MB V^T per head
__device__ __half g_e[(size_t)32 * 2048 * 2048];   // 256 MB exp(scores)
__device__ __half g_o[(size_t)4 * 2048 * 2048];    //  32 MB attn out (transposed)
__device__ float  g_l[(size_t)32 * 2048 * 16];     //   4 MB row-sum partials
__device__ float  g_p[(size_t)4 * 8192 * 256];     //  32 MB split-K partials
__device__ __half g_rq[2097152], g_rk[2097152], g_rv[2097152];
__device__ __half g_wq[524288], g_wk[524288], g_wv[524288], g_wo[524288];

__device__ __forceinline__ void cp_async16(uint32_t saddr, const void* g) {
    asm volatile("cp.async.cg.shared.global [%0], [%1], 16;" :: "r"(saddr), "l"(g));
}
#define CP_COMMIT() asm volatile("cp.async.commit_group;" ::: "memory")
#define CP_WAIT0()  asm volatile("cp.async.wait_group 0;" ::: "memory")
#define CP_WAIT1()  asm volatile("cp.async.wait_group 1;" ::: "memory")

__device__ __forceinline__ uint32_t smem_u32(const void* p) {
    uint32_t a;
    asm("{ .reg .u64 t; cvta.to.shared.u64 t, %1; cvt.u32.u64 %0, t; }"
        : "=r"(a) : "l"(p));
    return a;
}
__device__ __forceinline__ void mma_f16(float c[4],
    uint32_t a0, uint32_t a1, uint32_t a2, uint32_t a3,
    uint32_t b0, uint32_t b1)
{
    asm volatile(
        "mma.sync.aligned.m16n8k16.row.col.f32.f16.f16.f32 "
        "{%0,%1,%2,%3}, {%4,%5,%6,%7}, {%8,%9}, {%0,%1,%2,%3};\n"
        : "+f"(c[0]), "+f"(c[1]), "+f"(c[2]), "+f"(c[3])
        : "r"(a0), "r"(a1), "r"(a2), "r"(a3), "r"(b0), "r"(b1));
}
__device__ __forceinline__ void ldsm_x4(uint32_t& r0, uint32_t& r1,
                                        uint32_t& r2, uint32_t& r3, uint32_t a)
{
    asm volatile("ldmatrix.sync.aligned.m8n8.x4.shared.b16 {%0,%1,%2,%3}, [%4];"
                 : "=r"(r0), "=r"(r1), "=r"(r2), "=r"(r3) : "r"(a));
}

// ---------------------------------------------------------------------------
// Merged fp32 -> fp16 (RNE): 3 inputs (2M floats) + 4 weights (512K)
// ---------------------------------------------------------------------------
__global__ void __launch_bounds__(256) round_all(
    const float* __restrict__ q, const float* __restrict__ k,
    const float* __restrict__ v,
    const float* __restrict__ wq, const float* __restrict__ wk,
    const float* __restrict__ wv, const float* __restrict__ wo,
    __half* __restrict__ rq, __half* __restrict__ rk, __half* __restrict__ rv,
    __half* __restrict__ owq, __half* __restrict__ owk,
    __half* __restrict__ owv, __half* __restrict__ owo)
{
    int i = blockIdx.x * 256 + threadIdx.x;
    const float* src; __half* dst; int off;
    if (i < 1572864) {
        int s = i / 524288; off = i - s * 524288;
        src = s == 0 ? q : s == 1 ? k : v;
        dst = s == 0 ? rq : s == 1 ? rk : rv;
    } else {
        int j = i - 1572864;
        int s = j / 131072; off = j - s * 131072;
        src = s == 0 ? wq : s == 1 ? wk : s == 2 ? wv : wo;
        dst = s == 0 ? owq : s == 1 ? owk : s == 2 ? owv : owo;
    }
    float4 x = ((const float4*)src)[off];
    ((__half2*)dst)[2 * off]     = __floats2half2_rn(x.x, x.y);
    ((__half2*)dst)[2 * off + 1] = __floats2half2_rn(x.z, x.w);
}

// ---------------------------------------------------------------------------
// V transpose per head (RAW-RESHAPE slice):
//   V_h[s][d] = v[z*524288 + s*256 + d]   (z = b*8 + h)
//   vt[z][d][s] = V_h[s][d]
// ---------------------------------------------------------------------------
__global__ void __launch_bounds__(256) transpose_v(
    const __half* __restrict__ v, __half* __restrict__ vt)
{
    __shared__ __half t[32][34];
    const int z = blockIdx.z;
    const int s0 = blockIdx.x * 32, d0 = blockIdx.y * 32;
    const int tx = threadIdx.x, ty = threadIdx.y;

    const __half* src = v + (size_t)z * 524288 + (size_t)s0 * 256 + d0;
#pragma unroll
    for (int i = ty; i < 32; i += 8)
        t[i][tx] = src[(size_t)i * 256 + tx];
    __syncthreads();
    __half* dst = vt + (size_t)z * 524288 + (size_t)d0 * 2048 + s0;
#pragma unroll
    for (int i = ty; i < 32; i += 8)
        dst[(size_t)i * 2048 + tx] = t[tx][i];
}

// ---------------------------------------------------------------------------
// Split-K reduction: out[i] = sum_s p[s][i] + bias[col]
// 2097152 floats, float4 granularity.
// ---------------------------------------------------------------------------
__global__ void __launch_bounds__(256) reduce_out(
    const float* __restrict__ p, const float* __restrict__ bias,
    float* __restrict__ out)
{
    int i = blockIdx.x * 256 + threadIdx.x;      // float4 index, 524288 total
    const float4* p0 = (const float4*)p;
    float4 a = p0[i];
    float4 b = p0[i + 524288];
    float4 c = p0[i + 2 * 524288];
    float4 d = p0[i + 3 * 524288];
    float4 bv = *(const float4*)(bias + (i & 63) * 4);
    float4 r;
    r.x = a.x + b.x + c.x + d.x + bv.x;
    r.y = a.y + b.y + c.y + d.y + bv.y;
    r.z = a.z + b.z + c.z + d.z + bv.z;
    r.w = a.w + b.w + c.w + d.w + bv.w;
    ((float4*)out)[i] = r;
}

// ---------------------------------------------------------------------------
// fp16 NT GEMM body (R15-proven): C[128y,128x] = A[M,K] @ B[N,K]^T
// A,B half K-contig; BK=64 halfs staged [128 rows][144 B]; fragments via
// ldmatrix.x4 (HW layout). fp32 accumulate.
// EPI 0: +bias -> half | 1: exp(acc/16) -> half E + fp32 l partials
// EPI 2: scale 1/l -> half | 3: (+bias) -> float
// ---------------------------------------------------------------------------
#define OP_BYTES    18432
#define STAGE_BYTES (2 * OP_BYTES)
#define RED_OFF     (2 * STAGE_BYTES / 4)          // float index
#define GEMM_SMEM   (2 * STAGE_BYTES + 1024)       // 74752 B -> 3 CTAs/SM

template<int EPI>
__device__ __forceinline__ void gemm_body(
    const __half* __restrict__ A, const __half* __restrict__ B,
    const float* __restrict__ bias, void* __restrict__ Cv,
    float* __restrict__ lbase,
    int K, int lda, int ldb, int ldc, int lx)
{
    extern __shared__ __align__(16) float smem[];
    const uint32_t sbase = smem_u32(smem);
    const int tid  = threadIdx.x;
    const int lane = tid & 31;
    const int warp = tid >> 5;
    const int g = lane >> 2;
    const int t = lane & 3;
    const int wm0 = (warp >> 1) * 64;
    const int wn0 = (warp & 1) * 64;

    const int row0 = blockIdx.y * 128;
    const int col0 = blockIdx.x * 128;
    A += (size_t)row0 * lda;
    B += (size_t)col0 * ldb;
    const int nch = K >> 6;

    if (EPI == 2) {             // prologue: 1/l per row
        if (tid < 128) {
            const float* lp = lbase + (size_t)(row0 + tid) * 16;
            float4 a4 = *(const float4*)(lp);
            float4 b4 = *(const float4*)(lp + 4);
            float4 c4 = *(const float4*)(lp + 8);
            float4 d4 = *(const float4*)(lp + 12);
            float s = (a4.x + a4.y + a4.z + a4.w) + (b4.x + b4.y + b4.z + b4.w)
                    + (c4.x + c4.y + c4.z + c4.w) + (d4.x + d4.y + d4.z + d4.w);
            smem[RED_OFF + tid] = 1.0f / s;
        }
    }

    const int ar = tid >> 3, ac = tid & 7;

    auto stage = [&](int chunk) {
        const uint32_t abuf = sbase + (chunk & 1) * STAGE_BYTES;
        const uint32_t bbuf = abuf + OP_BYTES;
        const __half* Ak = A + chunk * 64;
        const __half* Bk = B + chunk * 64;
#pragma unroll
        for (int i = 0; i < 8; i++) {
            int r = ar + i * 16;
            cp_async16(abuf + r * 144 + ac * 16, Ak + (size_t)r * lda + ac * 8);
            cp_async16(bbuf + r * 144 + ac * 16, Bk + (size_t)r * ldb + ac * 8);
        }
        CP_COMMIT();
    };

    // ldmatrix lane->address selectors (R13-validated)
    const int a_row = ((lane >> 3) & 1) * 8 + (lane & 7);
    const int a_k   = (lane >> 4) * 8;
    const int b_n   = (lane >> 4) * 8 + (lane & 7);
    const int b_k   = ((lane >> 3) & 1) * 8;

    float acc[4][8][4];
#pragma unroll
    for (int i = 0; i < 4; i++)
#pragma unroll
        for (int j = 0; j < 8; j++)
#pragma unroll
            for (int l = 0; l < 4; l++) acc[i][j][l] = 0.0f;

    stage(0);
    for (int i = 0; i < nch; i++) {
        if (i + 1 < nch) { stage(i + 1); CP_WAIT1(); }
        else             { CP_WAIT0(); }
        __syncthreads();

        const uint32_t As = sbase + (i & 1) * STAGE_BYTES;
        const uint32_t Bs = As + OP_BYTES;
#pragma unroll
        for (int ks = 0; ks < 64; ks += 16) {
            uint32_t bf[8][2];
#pragma unroll
            for (int np = 0; np < 4; np++) {
                uint32_t baddr = Bs +
                    (uint32_t)((wn0 + np * 16 + b_n) * 144 + (ks + b_k) * 2);
                ldsm_x4(bf[2 * np][0], bf[2 * np][1],
                        bf[2 * np + 1][0], bf[2 * np + 1][1], baddr);
            }
#pragma unroll
            for (int mt = 0; mt < 4; mt++) {
                uint32_t aaddr = As +
                    (uint32_t)((wm0 + mt * 16 + a_row) * 144 + (ks + a_k) * 2);
                uint32_t a0, a1, a2, a3;
                ldsm_x4(a0, a1, a2, a3, aaddr);
#pragma unroll
                for (int nt = 0; nt < 8; nt++)
                    mma_f16(acc[mt][nt], a0, a1, a2, a3, bf[nt][0], bf[nt][1]);
            }
        }
        __syncthreads();
    }

    // ------------------- epilogues -------------------
    if (EPI == 1) {
        __half* C = (__half*)Cv;
        float* rs2 = smem + RED_OFF;          // [128][2]
#pragma unroll
        for (int mt = 0; mt < 4; mt++) {
            float ra = 0.0f, rb = 0.0f;
            int rA = row0 + wm0 + mt * 16 + g;
#pragma unroll
            for (int nt = 0; nt < 8; nt++) {
                int c = col0 + wn0 + nt * 8 + 2 * t;
                float e0 = __expf(acc[mt][nt][0] * 0.0625f);
                float e1 = __expf(acc[mt][nt][1] * 0.0625f);
                float e2 = __expf(acc[mt][nt][2] * 0.0625f);
                float e3 = __expf(acc[mt][nt][3] * 0.0625f);
                ra += e0 + e1;
                rb += e2 + e3;
                *(__half2*)(C + (size_t)rA * ldc + c) = __floats2half2_rn(e0, e1);
                *(__half2*)(C + (size_t)(rA + 8) * ldc + c) = __floats2half2_rn(e2, e3);
            }
            ra += __shfl_xor_sync(0xffffffffu, ra, 1);
            ra += __shfl_xor_sync(0xffffffffu, ra, 2);
            rb += __shfl_xor_sync(0xffffffffu, rb, 1);
            rb += __shfl_xor_sync(0xffffffffu, rb, 2);
            if (t == 0) {
                rs2[(wm0 + mt * 16 + g) * 2 + (warp & 1)]     = ra;
                rs2[(wm0 + mt * 16 + g + 8) * 2 + (warp & 1)] = rb;
            }
        }
        __syncthreads();
        if (tid < 128) {
            lbase[(size_t)(row0 + tid) * 16 + lx] =
                rs2[tid * 2] + rs2[tid * 2 + 1];
        }
        return;
    }

#pragma unroll
    for (int mt = 0; mt < 4; mt++) {
        float lv0 = 1.0f, lv1 = 1.0f;
        if (EPI == 2) {
            lv0 = smem[RED_OFF + wm0 + mt * 16 + g];
            lv1 = smem[RED_OFF + wm0 + mt * 16 + g + 8];
        }
#pragma unroll
        for (int nt = 0; nt < 8; nt++) {
            int r = row0 + wm0 + mt * 16 + g;
            int c = col0 + wn0 + nt * 8 + 2 * t;
            float b0v = ((EPI == 0 || EPI == 3) && bias) ? bias[c]     : 0.0f;
            float b1v = ((EPI == 0 || EPI == 3) && bias) ? bias[c + 1] : 0.0f;
            float v0x = acc[mt][nt][0] * lv0 + b0v;
            float v0y = acc[mt][nt][1] * lv0 + b1v;
            float v1x = acc[mt][nt][2] * lv1 + b0v;
            float v1y = acc[mt][nt][3] * lv1 + b1v;
            if (EPI == 3) {
                float* C = (float*)Cv;
                *(float2*)(C + (size_t)r * ldc + c)       = make_float2(v0x, v0y);
                *(float2*)(C + (size_t)(r + 8) * ldc + c) = make_float2(v1x, v1y);
            } else {
                __half* C = (__half*)Cv;
                *(__half2*)(C + (size_t)r * ldc + c)       = __floats2half2_rn(v0x, v0y);
                *(__half2*)(C + (size_t)(r + 8) * ldc + c) = __floats2half2_rn(v1x, v1y);
            }
        }
    }
}

// ---------------------------------------------------------------------------
// wrappers (3 CTAs/SM, R15-proven)
// ---------------------------------------------------------------------------
template<int EPI>
__global__ void __launch_bounds__(128, 3) gemm_ws(
    const __half* __restrict__ A, const __half* __restrict__ B,
    const float* __restrict__ bias, void* __restrict__ Cv,
    float* __restrict__ lbuf,
    int K, int lda, int ldb, int ldc,
    long long sA, long long sB, int Hp, long long sC_b, long long sC_h)
{
    const int z = blockIdx.z;
    long long coff = (long long)(z / Hp) * sC_b + (long long)(z % Hp) * sC_h;
    void* C = (EPI == 3) ? (void*)((float*)Cv + coff)
                         : (void*)((__half*)Cv + coff);
    gemm_body<EPI>(A + (long long)z * sA, B + (long long)z * sB, bias, C,
                   lbuf ? lbuf + (size_t)z * 2048 * 16 : nullptr,
                   K, lda, ldb, ldc, blockIdx.x);
}

__global__ void __launch_bounds__(128, 3) gemm_qkv(
    const __half* A0, const __half* A1, const __half* A2,
    const __half* W0, const __half* W1, const __half* W2,
    const float* b0, const float* b1, const float* b2,
    __half* C0, __half* C1, __half* C2,
    int K, int lda, int ldb, int ldc)
{
    const int z = blockIdx.z;
    const __half* A = z == 0 ? A0 : z == 1 ? A1 : A2;
    const __half* W = z == 0 ? W0 : z == 1 ? W1 : W2;
    const float* bb = z == 0 ? b0 : z == 1 ? b1 : b2;
    __half* C = z == 0 ? C0 : z == 1 ? C1 : C2;
    gemm_body<0>(A, W, bb, C, nullptr, K, lda, ldb, ldc, 0);
}

// ---------------------------------------------------------------------------
extern "C" void kernel_launch(void* const* d_in, const int* in_sizes, int n_in,
                              void* d_out, int out_size)
{
    const float* query = (const float*)d_in[0];
    const float* key   = (const float*)d_in[1];
    const float* vals  = (const float*)d_in[2];
    const float* Wq    = (const float*)d_in[3];
    const float* bq    = (const float*)d_in[4];
    const float* Wk    = (const float*)d_in[5];
    const float* bk    = (const float*)d_in[6];
    const float* Wv    = (const float*)d_in[7];
    const float* bv    = (const float*)d_in[8];
    const float* Wo    = (const float*)d_in[9];
    const float* bo    = (const float*)d_in[10];
    float* out = (float*)d_out;

    __half *q, *k, *v, *vt, *e, *o, *rq, *rk, *rv, *wq, *wk, *wv, *wo;
    float *l, *p;
    cudaGetSymbolAddress((void**)&q,  g_q);
    cudaGetSymbolAddress((void**)&k,  g_k);
    cudaGetSymbolAddress((void**)&v,  g_v);
    cudaGetSymbolAddress((void**)&vt, g_vt);
    cudaGetSymbolAddress((void**)&e,  g_e);
    cudaGetSymbolAddress((void**)&o,  g_o);
    cudaGetSymbolAddress((void**)&l,  g_l);
    cudaGetSymbolAddress((void**)&p,  g_p);
    cudaGetSymbolAddress((void**)&rq, g_rq);
    cudaGetSymbolAddress((void**)&rk, g_rk);
    cudaGetSymbolAddress((void**)&rv, g_rv);
    cudaGetSymbolAddress((void**)&wq, g_wq);
    cudaGetSymbolAddress((void**)&wk, g_wk);
    cudaGetSymbolAddress((void**)&wv, g_wv);
    cudaGetSymbolAddress((void**)&wo, g_wo);

    cudaFuncSetAttribute(gemm_qkv,
                         cudaFuncAttributeMaxDynamicSharedMemorySize, GEMM_SMEM);
    cudaFuncSetAttribute(gemm_ws<1>,
                         cudaFuncAttributeMaxDynamicSharedMemorySize, GEMM_SMEM);
    cudaFuncSetAttribute(gemm_ws<2>,
                         cudaFuncAttributeMaxDynamicSharedMemorySize, GEMM_SMEM);
    cudaFuncSetAttribute(gemm_ws<3>,
                         cudaFuncAttributeMaxDynamicSharedMemorySize, GEMM_SMEM);

    const int B = B_, S = S_, D = D_, HD = HD_;
    dim3 blk(128);
    size_t sm = GEMM_SMEM;

    // 0. fp32 -> fp16 (RNE)
    round_all<<<8192, 256>>>(query, key, vals, Wq, Wk, Wv, Wo,
                             rq, rk, rv, wq, wk, wv, wo);

    // 1. merged Q/K/V projections, K=256 -> half
    dim3 gp(HD / 128, (B * S) / 128, 3);
    gemm_qkv<<<gp, blk, sm>>>(rq, rk, rv, wq, wk, wv, bq, bk, bv,
                              q, k, v, D, D, D, HD);

    // 2. V transpose per head (raw-reshape slice) -> vt[z][d][s]
    transpose_v<<<dim3(S / 32, D / 32, B * H_), dim3(32, 8)>>>(v, vt);

    // 3. E = exp(Q_h K_h^T / 16) + l partials, K=256 (half E)
    dim3 gs(S / 128, S / 128, B * H_);
    gemm_ws<1><<<gs, blk, sm>>>(q, k, nullptr, e, l,
        D, D, D, S,
        (long long)S * D, (long long)S * D, 1, (long long)S * S, 0);

    // 4. O = (E VT^T) / l -> transposed layout, K=2048, ldb=2048
    dim3 gv(D / 128, S / 128, B * H_);
    gemm_ws<2><<<gv, blk, sm>>>(e, vt, nullptr, o, l,
        S, S, S, HD,
        (long long)S * S, (long long)D * S,
        H_, (long long)S * HD, (long long)D);

    // 5. split-K(4) out-projection: partials[z] = o[:, z*512:(z+1)*512] @ Wo^T
    dim3 gf(D / 128, (B * S) / 128, 4);
    gemm_ws<3><<<gf, blk, sm>>>(o, wo, nullptr, p, nullptr,
        512, HD, HD, D,
        512, 512, 1, (long long)8192 * 256, 0);

    // 6. y = sum partials + bo
    reduce_out<<<2048, 256>>>(p, bo, out);
}